// round 10
// baseline (speedup 1.0000x reference)
#include <cuda_runtime.h>
#include <cuda_bf16.h>
#include <math.h>

// Problem constants
#define NB   64
#define LSEQ 512
#define HD   1024
#define NBLK 128          // persistent blocks; block bx owns out cols [8bx, 8bx+8)
#define LH   (LSEQ * HD)

typedef unsigned long long ULL;

// Barrier counters: 8 spread arrival counters (32B apart), monotonic across
// replays. Per replay: 512 rounds x 16 arrivals each => +8192 per counter.
__device__ unsigned g_s8[8 * 8];
__device__ unsigned g_epoch;   // completed replay count

// ---------------------------------------------------------------------------
// Packed f32x2 helpers (FFMA2 — 2 exact fp32 MACs per issue)
// ---------------------------------------------------------------------------
__device__ __forceinline__ void ffma2(ULL& d, ULL a, ULL b)
{
    asm("fma.rn.f32x2 %0, %1, %2, %0;" : "+l"(d) : "l"(a), "l"(b));
}
__device__ __forceinline__ ULL rep2(float v)
{
    ULL r;
    asm("mov.b64 %0, {%1, %1};" : "=l"(r) : "f"(v));
    return r;
}
__device__ __forceinline__ float2 unpack2(ULL v)
{
    float2 f;
    asm("mov.b64 {%0, %1}, %2;" : "=f"(f.x), "=f"(f.y) : "l"(v));
    return f;
}

// ---------------------------------------------------------------------------
// Kernel 1: xh[m][o] = sum_h emb[x[m]][h] * Wxh[o][h] + bxh[o] + bhh[o]
// (unchanged from R8 — 128x128 tile, 8x8 microtile on f32x2)
// ---------------------------------------------------------------------------
__global__ __launch_bounds__(256) void xh_kernel(
    const int* __restrict__ x, const float* __restrict__ emb,
    const float* __restrict__ Wxh, const float* __restrict__ bxh,
    const float* __restrict__ bhh, float* __restrict__ out)
{
    __shared__ float As[16][132];
    __shared__ float Bs[16][132];
    __shared__ int   toks[128];

    const int m0 = blockIdx.y * 128;
    const int o0 = blockIdx.x * 128;
    const int tid = threadIdx.x;

    if (tid < 128) toks[tid] = x[m0 + tid];
    __syncthreads();

    const int lr  = tid & 127;
    const int lkq = (tid >> 7) << 3;
    const int tm  = (tid >> 4) << 3;
    const int tc  = (tid & 15) << 2;

    const float* Erow = emb + (size_t)toks[lr] * HD + lkq;
    const float* Wrow = Wxh + (size_t)(o0 + lr) * HD + lkq;

    ULL acc[8][4];
    #pragma unroll
    for (int i = 0; i < 8; i++)
        #pragma unroll
        for (int j = 0; j < 4; j++) acc[i][j] = 0ULL;

    for (int k0 = 0; k0 < HD; k0 += 16) {
        const float4 a0 = *(const float4*)(Erow + k0);
        const float4 a1 = *(const float4*)(Erow + k0 + 4);
        const float4 b0 = *(const float4*)(Wrow + k0);
        const float4 b1 = *(const float4*)(Wrow + k0 + 4);
        __syncthreads();
        As[lkq + 0][lr] = a0.x; As[lkq + 1][lr] = a0.y;
        As[lkq + 2][lr] = a0.z; As[lkq + 3][lr] = a0.w;
        As[lkq + 4][lr] = a1.x; As[lkq + 5][lr] = a1.y;
        As[lkq + 6][lr] = a1.z; As[lkq + 7][lr] = a1.w;
        Bs[lkq + 0][lr] = b0.x; Bs[lkq + 1][lr] = b0.y;
        Bs[lkq + 2][lr] = b0.z; Bs[lkq + 3][lr] = b0.w;
        Bs[lkq + 4][lr] = b1.x; Bs[lkq + 5][lr] = b1.y;
        Bs[lkq + 6][lr] = b1.z; Bs[lkq + 7][lr] = b1.w;
        __syncthreads();

        #pragma unroll
        for (int kk = 0; kk < 16; kk++) {
            const float4 av0 = *(const float4*)&As[kk][tm];
            const float4 av1 = *(const float4*)&As[kk][tm + 4];
            ULL ar[8];
            ar[0] = rep2(av0.x); ar[1] = rep2(av0.y);
            ar[2] = rep2(av0.z); ar[3] = rep2(av0.w);
            ar[4] = rep2(av1.x); ar[5] = rep2(av1.y);
            ar[6] = rep2(av1.z); ar[7] = rep2(av1.w);
            const ulonglong2 bq0 = *(const ulonglong2*)&Bs[kk][tc];
            const ulonglong2 bq1 = *(const ulonglong2*)&Bs[kk][64 + tc];
            #pragma unroll
            for (int i = 0; i < 8; i++) {
                ffma2(acc[i][0], ar[i], bq0.x);
                ffma2(acc[i][1], ar[i], bq0.y);
                ffma2(acc[i][2], ar[i], bq1.x);
                ffma2(acc[i][3], ar[i], bq1.y);
            }
        }
    }

    const float4 bxa = *(const float4*)&bxh[o0 + tc];
    const float4 bxb = *(const float4*)&bxh[o0 + 64 + tc];
    const float4 bha = *(const float4*)&bhh[o0 + tc];
    const float4 bhb = *(const float4*)&bhh[o0 + 64 + tc];
    const float bs0[4] = {bxa.x + bha.x, bxa.y + bha.y, bxa.z + bha.z, bxa.w + bha.w};
    const float bs1[4] = {bxb.x + bhb.x, bxb.y + bhb.y, bxb.z + bhb.z, bxb.w + bhb.w};

    #pragma unroll
    for (int i = 0; i < 8; i++) {
        const float2 p0 = unpack2(acc[i][0]);
        const float2 p1 = unpack2(acc[i][1]);
        const float2 p2 = unpack2(acc[i][2]);
        const float2 p3 = unpack2(acc[i][3]);
        float4 v0, v1;
        v0.x = p0.x + bs0[0]; v0.y = p0.y + bs0[1];
        v0.z = p1.x + bs0[2]; v0.w = p1.y + bs0[3];
        v1.x = p2.x + bs1[0]; v1.y = p2.y + bs1[1];
        v1.z = p3.x + bs1[2]; v1.w = p3.y + bs1[3];
        float* po = &out[(size_t)(m0 + tm + i) * HD + o0 + tc];
        *(float4*)po        = v0;
        *(float4*)(po + 64) = v1;
    }
}

// ---------------------------------------------------------------------------
// Single global barrier: 128 arrivals spread over 8 counters; threads 0..7
// poll one counter each. target is absolute (monotonic across replays).
// ---------------------------------------------------------------------------
__device__ __forceinline__ void gbar(int bx, unsigned target)
{
    __syncthreads();
    if (threadIdx.x == 0) {
        __threadfence();
        atomicAdd(&g_s8[(bx & 7) * 8], 1u);
    }
    if (threadIdx.x < 8) {
        while ((int)(*(volatile unsigned*)&g_s8[threadIdx.x * 8] - target) < 0) { }
    }
    __threadfence();
    __syncthreads();
}

// ---------------------------------------------------------------------------
// Kernel 2: full-K persistent recurrence. Block bx owns out cols [8bx,8bx+8):
// per step streams ALL of h_{t-1} (256KB) from L2 in 8 chunks of 128k,
// warp w handles k-strip [16w,16w+16) of each chunk (warp-coherent kk),
// lanes = 8 n-groups x 4 o-pairs. Warp partials reduced in smem, + xh,
// tanh, write h_t, ONE global barrier.
//
// Dynamic smem: Bs [1024][10] | As [8 warps][16][72] | Pr [8][64][10]
// As column map col(n) = n + 4*(n>>5): A-reads are 2 conflict-free LDS.128;
// staging is warp-private (syncwarp only) with phase-staggered STS.32.
// ---------------------------------------------------------------------------
__global__ __launch_bounds__(256) void rnn_persistent(
    const float* __restrict__ Whh, float* __restrict__ out)
{
    extern __shared__ float sm[];
    float* Bsm = sm;                        // 1024*10
    float* Asm = sm + 1024 * 10;            // 8*16*72
    float* Prm = Asm + 8 * 16 * 72;         // 8*64*10

    const int bx  = blockIdx.x;
    const int tid = threadIdx.x;
    const int w   = tid >> 5;
    const int l   = tid & 31;
    const int a   = l >> 2;                 // n-group: rows 8a..8a+8
    const int b   = l & 3;                  // o-pair: cols 2b, 2b+1
    const int ca  = 8 * a + 4 * (a >> 2);   // swizzled A col base
    const int bo  = 2 * b;
    const int o0  = bx * 8;

    // Load Whh rows [o0, o0+8) once: Bsm[k*10 + o]
    {
        const int o = tid & 7, ks = tid >> 3;      // 32 k-strips of 32
        const float* wr = Whh + (size_t)(o0 + o) * HD + ks * 32;
        #pragma unroll
        for (int q = 0; q < 8; q++) {
            const float4 v = *(const float4*)(wr + q * 4);
            const int k = ks * 32 + q * 4;
            Bsm[(k + 0) * 10 + o] = v.x; Bsm[(k + 1) * 10 + o] = v.y;
            Bsm[(k + 2) * 10 + o] = v.z; Bsm[(k + 3) * 10 + o] = v.w;
        }
    }

    __shared__ unsigned s_e;
    if (tid == 0) s_e = *(volatile unsigned*)&g_epoch;
    __syncthreads();
    const unsigned ebase = 8192u * s_e;

    // reduce mapping: thread -> (n = tid>>2, o-pair rob)
    const int rn  = tid >> 2;
    const int rob = (tid & 3) << 1;

    // --- t = 0: h_0 = tanh(xh_0) on my 8 columns ---
    {
        float* p = out + (size_t)rn * LH + o0 + rob;
        float2 v = *(float2*)p;
        v.x = tanhf(v.x); v.y = tanhf(v.y);
        *(float2*)p = v;
    }
    gbar(bx, ebase + 16u);

    const int cr0 = bx & 7;    // chunk stagger per block

    for (int t = 1; t < LSEQ; t++) {
        const float* hbase = out + (size_t)(t - 1) * HD;

        ULL acc[4][2];
        #pragma unroll
        for (int j = 0; j < 4; j++) { acc[j][0] = 0ULL; acc[j][1] = 0ULL; }

        // register chunk buffers: rows l (fb[par][0..15]) and l+32 (fb[par][16..31])
        float fb[2][32];

        // preload chunk 0
        {
            const int kb = cr0 * 128 + 16 * w;
            const float* p0 = hbase + (size_t)l * LH + kb;
            const float* p1 = p0 + (size_t)32 * LH;
            #pragma unroll
            for (int q = 0; q < 4; q++) {
                *(float4*)&fb[0][q * 4]      = __ldcg((const float4*)(p0 + q * 4));
                *(float4*)&fb[0][16 + q * 4] = __ldcg((const float4*)(p1 + q * 4));
            }
        }

        #pragma unroll
        for (int c = 0; c < 8; c++) {
            const int par = c & 1;
            const int cr  = (cr0 + c) & 7;
            const int kb  = cr * 128 + 16 * w;

            __syncwarp();   // prior inner reads of Asm[w] complete
            // phase-staggered store: k=i row l (col l), k=(i+8)&15 row l+32 (col l+36)
            float* aw = Asm + w * 16 * 72;
            #pragma unroll
            for (int i = 0; i < 16; i++) {
                aw[i * 72 + l] = fb[par][i];
                const int i2 = (i + 8) & 15;
                aw[i2 * 72 + l + 36] = fb[par][16 + i2];
            }
            // prefetch next chunk
            if (c < 7) {
                const int kb2 = (((cr0 + c + 1) & 7) * 128) + 16 * w;
                const float* p0 = hbase + (size_t)l * LH + kb2;
                const float* p1 = p0 + (size_t)32 * LH;
                #pragma unroll
                for (int q = 0; q < 4; q++) {
                    *(float4*)&fb[par ^ 1][q * 4]      = __ldcg((const float4*)(p0 + q * 4));
                    *(float4*)&fb[par ^ 1][16 + q * 4] = __ldcg((const float4*)(p1 + q * 4));
                }
            }
            __syncwarp();   // staged data visible to warp

            #pragma unroll
            for (int kk = 0; kk < 16; kk++) {
                const float* ap = aw + kk * 72;
                const ulonglong2 ua = *(const ulonglong2*)(ap + ca);      // n pairs 0,1
                const ulonglong2 ub = *(const ulonglong2*)(ap + ca + 4);  // n pairs 2,3
                const float2 bb = *(const float2*)(Bsm + (size_t)(kb + kk) * 10 + bo);
                const ULL b0 = rep2(bb.x);
                const ULL b1 = rep2(bb.y);
                ffma2(acc[0][0], ua.x, b0); ffma2(acc[0][1], ua.x, b1);
                ffma2(acc[1][0], ua.y, b0); ffma2(acc[1][1], ua.y, b1);
                ffma2(acc[2][0], ub.x, b0); ffma2(acc[2][1], ub.x, b1);
                ffma2(acc[3][0], ub.y, b0); ffma2(acc[3][1], ub.y, b1);
            }
        }

        // warp partials -> Prm[w][n][o]
        #pragma unroll
        for (int j = 0; j < 4; j++) {
            const float2 c0 = unpack2(acc[j][0]);   // (n even, n odd) @ o = bo
            const float2 c1 = unpack2(acc[j][1]);   // (n even, n odd) @ o = bo+1
            const int n = 8 * a + 2 * j;
            float2 ev, od;
            ev.x = c0.x; ev.y = c1.x;
            od.x = c0.y; od.y = c1.y;
            *(float2*)&Prm[(w * 64 + n) * 10 + bo]     = ev;
            *(float2*)&Prm[(w * 64 + n + 1) * 10 + bo] = od;
        }
        __syncthreads();

        // reduce 8 warps + xh, tanh, write h_t
        {
            float2 s = make_float2(0.f, 0.f);
            #pragma unroll
            for (int ww = 0; ww < 8; ww++) {
                const float2 v = *(const float2*)&Prm[(ww * 64 + rn) * 10 + rob];
                s.x += v.x; s.y += v.y;
            }
            float* po = out + (size_t)rn * LH + (size_t)t * HD + o0 + rob;
            const float2 xh = *(const float2*)po;
            float2 h;
            h.x = tanhf(s.x + xh.x);
            h.y = tanhf(s.y + xh.y);
            *(float2*)po = h;
        }

        gbar(bx, ebase + 16u * (unsigned)(t + 1));
    }

    // epoch bump: all 512 rounds complete for all blocks (final gbar passed)
    if (bx == 0 && tid == 0) *(volatile unsigned*)&g_epoch = s_e + 1u;
}

// ---------------------------------------------------------------------------
// Launch: metadata order is x, emb, W_hh_w, W_hh_b, W_xh_w, W_xh_b.
// Graph: exactly 2 kernel nodes.
// ---------------------------------------------------------------------------
#define RNN_SMEM_BYTES ((1024 * 10 + 8 * 16 * 72 + 8 * 64 * 10) * 4)

extern "C" void kernel_launch(void* const* d_in, const int* in_sizes, int n_in,
                              void* d_out, int out_size)
{
    const int*   x     = (const int*)  d_in[0];
    const float* emb   = (const float*)d_in[1];
    const float* Whh_w = (const float*)d_in[2];
    const float* Whh_b = (const float*)d_in[3];
    const float* Wxh_w = (const float*)d_in[4];
    const float* Wxh_b = (const float*)d_in[5];
    float* out = (float*)d_out;

    dim3 g1(HD / 128, (NB * LSEQ) / 128);   // (8, 256)
    xh_kernel<<<g1, 256>>>(x, emb, Wxh_w, Wxh_b, Whh_b, out);

    cudaFuncSetAttribute(rnn_persistent,
                         cudaFuncAttributeMaxDynamicSharedMemorySize,
                         RNN_SMEM_BYTES);
    rnn_persistent<<<NBLK, 256, RNN_SMEM_BYTES>>>(Whh_w, out);
}

// round 11
// speedup vs baseline: 1.7125x; 1.7125x over previous
#include <cuda_runtime.h>
#include <cuda_bf16.h>
#include <math.h>

// Problem constants
#define NB   64
#define LSEQ 512
#define HD   1024
#define LH   (LSEQ * HD)
#define NBLK 128          // 4 n-groups (16 rows) x 32 o-tiles (32 cols)

typedef unsigned long long ULL;

// Per-ng arrival counters (32B apart), monotonic across replays:
// 32 arrivals x 512 rounds = +16384 per replay.
__device__ unsigned g_cnt[4 * 8];
__device__ unsigned g_end;     // end-of-replay quiesce
__device__ unsigned g_epoch;   // completed replay count

// ---------------------------------------------------------------------------
// Packed f32x2 helpers (FFMA2 — 2 exact fp32 MACs per issue)
// ---------------------------------------------------------------------------
__device__ __forceinline__ void ffma2(ULL& d, ULL a, ULL b)
{
    asm("fma.rn.f32x2 %0, %1, %2, %0;" : "+l"(d) : "l"(a), "l"(b));
}
__device__ __forceinline__ ULL rep2(float v)
{
    ULL r;
    asm("mov.b64 %0, {%1, %1};" : "=l"(r) : "f"(v));
    return r;
}
__device__ __forceinline__ ULL pack2(float x, float y)
{
    ULL r;
    asm("mov.b64 %0, {%1, %2};" : "=l"(r) : "f"(x), "f"(y));
    return r;
}
__device__ __forceinline__ float2 unpack2(ULL v)
{
    float2 f;
    asm("mov.b64 {%0, %1}, %2;" : "=f"(f.x), "=f"(f.y) : "l"(v));
    return f;
}

// ---------------------------------------------------------------------------
// Kernel 1: xh[m][o] = sum_h emb[x[m]][h] * Wxh[o][h] + bxh[o] + bhh[o]
// (unchanged from R8 — 128x128 tile, 8x8 microtile on f32x2)
// ---------------------------------------------------------------------------
__global__ __launch_bounds__(256) void xh_kernel(
    const int* __restrict__ x, const float* __restrict__ emb,
    const float* __restrict__ Wxh, const float* __restrict__ bxh,
    const float* __restrict__ bhh, float* __restrict__ out)
{
    __shared__ float As[16][132];
    __shared__ float Bs[16][132];
    __shared__ int   toks[128];

    const int m0 = blockIdx.y * 128;
    const int o0 = blockIdx.x * 128;
    const int tid = threadIdx.x;

    if (tid < 128) toks[tid] = x[m0 + tid];
    __syncthreads();

    const int lr  = tid & 127;
    const int lkq = (tid >> 7) << 3;
    const int tm  = (tid >> 4) << 3;
    const int tc  = (tid & 15) << 2;

    const float* Erow = emb + (size_t)toks[lr] * HD + lkq;
    const float* Wrow = Wxh + (size_t)(o0 + lr) * HD + lkq;

    ULL acc[8][4];
    #pragma unroll
    for (int i = 0; i < 8; i++)
        #pragma unroll
        for (int j = 0; j < 4; j++) acc[i][j] = 0ULL;

    for (int k0 = 0; k0 < HD; k0 += 16) {
        const float4 a0 = *(const float4*)(Erow + k0);
        const float4 a1 = *(const float4*)(Erow + k0 + 4);
        const float4 b0 = *(const float4*)(Wrow + k0);
        const float4 b1 = *(const float4*)(Wrow + k0 + 4);
        __syncthreads();
        As[lkq + 0][lr] = a0.x; As[lkq + 1][lr] = a0.y;
        As[lkq + 2][lr] = a0.z; As[lkq + 3][lr] = a0.w;
        As[lkq + 4][lr] = a1.x; As[lkq + 5][lr] = a1.y;
        As[lkq + 6][lr] = a1.z; As[lkq + 7][lr] = a1.w;
        Bs[lkq + 0][lr] = b0.x; Bs[lkq + 1][lr] = b0.y;
        Bs[lkq + 2][lr] = b0.z; Bs[lkq + 3][lr] = b0.w;
        Bs[lkq + 4][lr] = b1.x; Bs[lkq + 5][lr] = b1.y;
        Bs[lkq + 6][lr] = b1.z; Bs[lkq + 7][lr] = b1.w;
        __syncthreads();

        #pragma unroll
        for (int kk = 0; kk < 16; kk++) {
            const float4 av0 = *(const float4*)&As[kk][tm];
            const float4 av1 = *(const float4*)&As[kk][tm + 4];
            ULL ar[8];
            ar[0] = rep2(av0.x); ar[1] = rep2(av0.y);
            ar[2] = rep2(av0.z); ar[3] = rep2(av0.w);
            ar[4] = rep2(av1.x); ar[5] = rep2(av1.y);
            ar[6] = rep2(av1.z); ar[7] = rep2(av1.w);
            const ulonglong2 bq0 = *(const ulonglong2*)&Bs[kk][tc];
            const ulonglong2 bq1 = *(const ulonglong2*)&Bs[kk][64 + tc];
            #pragma unroll
            for (int i = 0; i < 8; i++) {
                ffma2(acc[i][0], ar[i], bq0.x);
                ffma2(acc[i][1], ar[i], bq0.y);
                ffma2(acc[i][2], ar[i], bq1.x);
                ffma2(acc[i][3], ar[i], bq1.y);
            }
        }
    }

    const float4 bxa = *(const float4*)&bxh[o0 + tc];
    const float4 bxb = *(const float4*)&bxh[o0 + 64 + tc];
    const float4 bha = *(const float4*)&bhh[o0 + tc];
    const float4 bhb = *(const float4*)&bhh[o0 + 64 + tc];
    const float bs0[4] = {bxa.x + bha.x, bxa.y + bha.y, bxa.z + bha.z, bxa.w + bha.w};
    const float bs1[4] = {bxb.x + bhb.x, bxb.y + bhb.y, bxb.z + bhb.z, bxb.w + bhb.w};

    #pragma unroll
    for (int i = 0; i < 8; i++) {
        const float2 p0 = unpack2(acc[i][0]);
        const float2 p1 = unpack2(acc[i][1]);
        const float2 p2 = unpack2(acc[i][2]);
        const float2 p3 = unpack2(acc[i][3]);
        float4 v0, v1;
        v0.x = p0.x + bs0[0]; v0.y = p0.y + bs0[1];
        v0.z = p1.x + bs0[2]; v0.w = p1.y + bs0[3];
        v1.x = p2.x + bs1[0]; v1.y = p2.y + bs1[1];
        v1.z = p3.x + bs1[2]; v1.w = p3.y + bs1[3];
        float* po = &out[(size_t)(m0 + tm + i) * HD + o0 + tc];
        *(float4*)po        = v0;
        *(float4*)(po + 64) = v1;
    }
}

// ---------------------------------------------------------------------------
// Kernel 2: persistent recurrence, batch-row partitioned.
// Block bx: ng = bx>>5 (rows [16ng,16ng+16)), ot = bx&31 (cols [32ot,32ot+32)).
// W_hh slice [32 o][1024 k] resident in smem as k-pairs. Per step:
//   stage h_{t-1}[16 rows][1024] -> As2 (k-pair major),
//   full-K GEMM: warp = 128-k strip, lane = 4n x 4o microtile, FFMA2 on
//   (a-pair, b-pair) with horizontal add at the end,
//   8-warp smem reduce + xh + tanh -> out[n][t][o] in place,
//   ONE barrier over the 32 blocks sharing ng.
// Smem: Bs2 ULL[512][32] (128KB) | As2 ULL[512*17+..] (68KB) | Pr f[8][16][36]
// ---------------------------------------------------------------------------
#define RNN_SMEM_BYTES ((512 * 32 + 512 * 17 + 8) * 8 + 8 * 16 * 36 * 4)

__global__ __launch_bounds__(256) void rnn_persistent(
    const float* __restrict__ Whh, float* __restrict__ out)
{
    extern __shared__ char smraw[];
    ULL*   Bs2 = (ULL*)smraw;                 // [kp][o]   stride 32
    ULL*   As2 = Bs2 + 512 * 32;              // [kp][n]   stride 17 (pad)
    float* Pr  = (float*)(As2 + 512 * 17 + 8);// [w][n][o] stride 36

    const int bx  = blockIdx.x;
    const int ng  = bx >> 5;
    const int ot  = bx & 31;
    const int n0  = ng * 16;
    const int o0  = ot * 32;
    const int tid = threadIdx.x;
    const int w   = tid >> 5;
    const int lane = tid & 31;
    const int ogl = lane >> 2;    // 0..7  -> o cols [4ogl, 4ogl+4)
    const int ngl = lane & 3;     // 0..3  -> n rows [4ngl, 4ngl+4)

    // ---- load W_hh slice once: Bs2[kp*32 + o] = (W[o0+o][2kp], W[o0+o][2kp+1])
    {
        const int o   = tid & 31;
        const int its = tid >> 5;                 // 8 strips of 128 k
        const float* wr = Whh + (size_t)(o0 + o) * HD + its * 128;
        #pragma unroll
        for (int m = 0; m < 32; m++) {
            const float4 v = *(const float4*)(wr + 4 * m);
            const int kp = its * 64 + 2 * m;
            Bs2[(size_t)kp * 32 + o]       = pack2(v.x, v.y);
            Bs2[(size_t)(kp + 1) * 32 + o] = pack2(v.z, v.w);
        }
    }

    // ---- epoch -> counter base (stable: previous replay fully exited)
    __shared__ unsigned s_e;
    if (tid == 0) s_e = *(volatile unsigned*)&g_epoch;
    __syncthreads();
    const unsigned e = s_e;
    const unsigned base = 16384u * e;

    // reduce/tanh mapping: thread -> (row n0+rn, float2 at o0+ro)
    const int rn = tid >> 4;
    const int ro = (tid & 15) << 1;

    // stage mapping: thread -> (row, 4-float k chunk), lane-major k (coalesced)
    const int srow = tid >> 4;
    const int sk0  = (tid & 15) << 2;

    // ---- t = 0: h_0 = tanh(xh_0) on my slice ----
    {
        float* p = out + (size_t)(n0 + rn) * LH + o0 + ro;
        float2 v = *(float2*)p;
        v.x = tanhf(v.x); v.y = tanhf(v.y);
        *(float2*)p = v;
    }
    __threadfence();
    __syncthreads();
    if (tid == 0) atomicAdd(&g_cnt[ng * 8], 1u);

    for (int t = 1; t < LSEQ; t++) {
        // ---- wait: h_{t-1}[my rows][*] complete (32 arrivals per round) ----
        if (tid == 0) {
            const unsigned tgt = base + 32u * (unsigned)t;
            while ((int)(*(volatile unsigned*)&g_cnt[ng * 8] - tgt) < 0) { }
        }
        __syncthreads();
        __threadfence();

        // ---- stage h_{t-1}[16 rows][1024] into As2 (k-pair major) ----
        {
            const float* hp = out + (size_t)(n0 + srow) * LH
                                  + (size_t)(t - 1) * HD + sk0;
            #pragma unroll
            for (int it = 0; it < 16; it++) {
                const float4 v = *(const float4*)(hp + 64 * it);
                const int kp = (sk0 >> 1) + 32 * it;
                As2[(size_t)kp * 17 + srow]       = pack2(v.x, v.y);
                As2[(size_t)(kp + 1) * 17 + srow] = pack2(v.z, v.w);
            }
        }
        __syncthreads();

        // ---- full-K GEMM: warp strip kp in [64w, 64w+64) ----
        ULL acc[4][4];
        #pragma unroll
        for (int i = 0; i < 4; i++)
            #pragma unroll
            for (int j = 0; j < 4; j++) acc[i][j] = 0ULL;

        {
            const ULL* ap = As2 + (size_t)(64 * w) * 17 + 4 * ngl;
            const ULL* bp = Bs2 + (size_t)(64 * w) * 32 + 4 * ogl;
            #pragma unroll 4
            for (int kp = 0; kp < 64; kp++) {
                const ULL a0 = ap[0], a1 = ap[1], a2 = ap[2], a3 = ap[3];
                const ulonglong2 b01 = *(const ulonglong2*)(bp);
                const ulonglong2 b23 = *(const ulonglong2*)(bp + 2);
                ffma2(acc[0][0], a0, b01.x); ffma2(acc[0][1], a0, b01.y);
                ffma2(acc[0][2], a0, b23.x); ffma2(acc[0][3], a0, b23.y);
                ffma2(acc[1][0], a1, b01.x); ffma2(acc[1][1], a1, b01.y);
                ffma2(acc[1][2], a1, b23.x); ffma2(acc[1][3], a1, b23.y);
                ffma2(acc[2][0], a2, b01.x); ffma2(acc[2][1], a2, b01.y);
                ffma2(acc[2][2], a2, b23.x); ffma2(acc[2][3], a2, b23.y);
                ffma2(acc[3][0], a3, b01.x); ffma2(acc[3][1], a3, b01.y);
                ffma2(acc[3][2], a3, b23.x); ffma2(acc[3][3], a3, b23.y);
                ap += 17;
                bp += 32;
            }
        }

        // ---- horizontal add, park warp partials in Pr[w][n][o] ----
        #pragma unroll
        for (int i = 0; i < 4; i++)
            #pragma unroll
            for (int j = 0; j < 4; j++) {
                const float2 p = unpack2(acc[i][j]);
                Pr[(w * 16 + 4 * ngl + i) * 36 + 4 * ogl + j] = p.x + p.y;
            }
        __syncthreads();

        // ---- reduce 8 warps + xh, tanh, write h_t in place ----
        {
            float2 s = make_float2(0.f, 0.f);
            #pragma unroll
            for (int ww = 0; ww < 8; ww++) {
                const float2 v = *(const float2*)&Pr[(ww * 16 + rn) * 36 + ro];
                s.x += v.x; s.y += v.y;
            }
            float* po = out + (size_t)(n0 + rn) * LH + (size_t)t * HD + o0 + ro;
            const float2 xh = *(const float2*)po;
            float2 h;
            h.x = tanhf(s.x + xh.x);
            h.y = tanhf(s.y + xh.y);
            *(float2*)po = h;
        }

        __threadfence();
        __syncthreads();
        if (tid == 0) atomicAdd(&g_cnt[ng * 8], 1u);
    }

    // ---- end-of-replay quiesce: only block 0's thread 0 blocks ----
    if (tid == 0) atomicAdd(&g_end, 1u);
    if (bx == 0 && tid == 0) {
        const unsigned tgt = 128u * (e + 1u);
        while ((int)(*(volatile unsigned*)&g_end - tgt) < 0) { }
        *(volatile unsigned*)&g_epoch = e + 1u;
    }
}

// ---------------------------------------------------------------------------
// Launch: metadata order is x, emb, W_hh_w, W_hh_b, W_xh_w, W_xh_b.
// Graph: exactly 2 kernel nodes.
// ---------------------------------------------------------------------------
extern "C" void kernel_launch(void* const* d_in, const int* in_sizes, int n_in,
                              void* d_out, int out_size)
{
    const int*   x     = (const int*)  d_in[0];
    const float* emb   = (const float*)d_in[1];
    const float* Whh_w = (const float*)d_in[2];
    const float* Whh_b = (const float*)d_in[3];
    const float* Wxh_w = (const float*)d_in[4];
    const float* Wxh_b = (const float*)d_in[5];
    float* out = (float*)d_out;

    dim3 g1(HD / 128, (NB * LSEQ) / 128);   // (8, 256)
    xh_kernel<<<g1, 256>>>(x, emb, Wxh_w, Wxh_b, Whh_b, out);

    cudaFuncSetAttribute(rnn_persistent,
                         cudaFuncAttributeMaxDynamicSharedMemorySize,
                         RNN_SMEM_BYTES);
    rnn_persistent<<<NBLK, 256, RNN_SMEM_BYTES>>>(Whh_w, out);
}

// round 12
// speedup vs baseline: 1.7386x; 1.0152x over previous
#include <cuda_runtime.h>
#include <cuda_bf16.h>
#include <math.h>

// Problem constants
#define NB   64
#define LSEQ 512
#define HD   1024
#define LH   (LSEQ * HD)
#define NBLK 128          // 4 n-groups (16 rows) x 32 o-tiles (32 cols)

typedef unsigned long long ULL;

// Octet arrival counters: g_oct[ng][oct] (32B apart). Producer (ng,ot) arrives
// on oct = ot>>3 once per step => +512 per producer per replay => +4096/replay.
__device__ unsigned g_oct[4 * 4 * 8];
__device__ unsigned g_end;     // end-of-replay quiesce
__device__ unsigned g_epoch;   // completed replay count

// ---------------------------------------------------------------------------
// Packed f32x2 helpers (FFMA2 — 2 exact fp32 MACs per issue)
// ---------------------------------------------------------------------------
__device__ __forceinline__ void ffma2(ULL& d, ULL a, ULL b)
{
    asm("fma.rn.f32x2 %0, %1, %2, %0;" : "+l"(d) : "l"(a), "l"(b));
}
__device__ __forceinline__ ULL rep2(float v)
{
    ULL r;
    asm("mov.b64 %0, {%1, %1};" : "=l"(r) : "f"(v));
    return r;
}
__device__ __forceinline__ ULL pack2(float x, float y)
{
    ULL r;
    asm("mov.b64 %0, {%1, %2};" : "=l"(r) : "f"(x), "f"(y));
    return r;
}
__device__ __forceinline__ float2 unpack2(ULL v)
{
    float2 f;
    asm("mov.b64 {%0, %1}, %2;" : "=f"(f.x), "=f"(f.y) : "l"(v));
    return f;
}

// ---------------------------------------------------------------------------
// Kernel 1: xh[m][o] = sum_h emb[x[m]][h] * Wxh[o][h] + bxh[o] + bhh[o]
// (unchanged — 128x128 tile, 8x8 microtile on f32x2, at its FFMA2 floor)
// ---------------------------------------------------------------------------
__global__ __launch_bounds__(256) void xh_kernel(
    const int* __restrict__ x, const float* __restrict__ emb,
    const float* __restrict__ Wxh, const float* __restrict__ bxh,
    const float* __restrict__ bhh, float* __restrict__ out)
{
    __shared__ float As[16][132];
    __shared__ float Bs[16][132];
    __shared__ int   toks[128];

    const int m0 = blockIdx.y * 128;
    const int o0 = blockIdx.x * 128;
    const int tid = threadIdx.x;

    if (tid < 128) toks[tid] = x[m0 + tid];
    __syncthreads();

    const int lr  = tid & 127;
    const int lkq = (tid >> 7) << 3;
    const int tm  = (tid >> 4) << 3;
    const int tc  = (tid & 15) << 2;

    const float* Erow = emb + (size_t)toks[lr] * HD + lkq;
    const float* Wrow = Wxh + (size_t)(o0 + lr) * HD + lkq;

    ULL acc[8][4];
    #pragma unroll
    for (int i = 0; i < 8; i++)
        #pragma unroll
        for (int j = 0; j < 4; j++) acc[i][j] = 0ULL;

    for (int k0 = 0; k0 < HD; k0 += 16) {
        const float4 a0 = *(const float4*)(Erow + k0);
        const float4 a1 = *(const float4*)(Erow + k0 + 4);
        const float4 b0 = *(const float4*)(Wrow + k0);
        const float4 b1 = *(const float4*)(Wrow + k0 + 4);
        __syncthreads();
        As[lkq + 0][lr] = a0.x; As[lkq + 1][lr] = a0.y;
        As[lkq + 2][lr] = a0.z; As[lkq + 3][lr] = a0.w;
        As[lkq + 4][lr] = a1.x; As[lkq + 5][lr] = a1.y;
        As[lkq + 6][lr] = a1.z; As[lkq + 7][lr] = a1.w;
        Bs[lkq + 0][lr] = b0.x; Bs[lkq + 1][lr] = b0.y;
        Bs[lkq + 2][lr] = b0.z; Bs[lkq + 3][lr] = b0.w;
        Bs[lkq + 4][lr] = b1.x; Bs[lkq + 5][lr] = b1.y;
        Bs[lkq + 6][lr] = b1.z; Bs[lkq + 7][lr] = b1.w;
        __syncthreads();

        #pragma unroll
        for (int kk = 0; kk < 16; kk++) {
            const float4 av0 = *(const float4*)&As[kk][tm];
            const float4 av1 = *(const float4*)&As[kk][tm + 4];
            ULL ar[8];
            ar[0] = rep2(av0.x); ar[1] = rep2(av0.y);
            ar[2] = rep2(av0.z); ar[3] = rep2(av0.w);
            ar[4] = rep2(av1.x); ar[5] = rep2(av1.y);
            ar[6] = rep2(av1.z); ar[7] = rep2(av1.w);
            const ulonglong2 bq0 = *(const ulonglong2*)&Bs[kk][tc];
            const ulonglong2 bq1 = *(const ulonglong2*)&Bs[kk][64 + tc];
            #pragma unroll
            for (int i = 0; i < 8; i++) {
                ffma2(acc[i][0], ar[i], bq0.x);
                ffma2(acc[i][1], ar[i], bq0.y);
                ffma2(acc[i][2], ar[i], bq1.x);
                ffma2(acc[i][3], ar[i], bq1.y);
            }
        }
    }

    const float4 bxa = *(const float4*)&bxh[o0 + tc];
    const float4 bxb = *(const float4*)&bxh[o0 + 64 + tc];
    const float4 bha = *(const float4*)&bhh[o0 + tc];
    const float4 bhb = *(const float4*)&bhh[o0 + 64 + tc];
    const float bs0[4] = {bxa.x + bha.x, bxa.y + bha.y, bxa.z + bha.z, bxa.w + bha.w};
    const float bs1[4] = {bxb.x + bhb.x, bxb.y + bhb.y, bxb.z + bhb.z, bxb.w + bhb.w};

    #pragma unroll
    for (int i = 0; i < 8; i++) {
        const float2 p0 = unpack2(acc[i][0]);
        const float2 p1 = unpack2(acc[i][1]);
        const float2 p2 = unpack2(acc[i][2]);
        const float2 p3 = unpack2(acc[i][3]);
        float4 v0, v1;
        v0.x = p0.x + bs0[0]; v0.y = p0.y + bs0[1];
        v0.z = p1.x + bs0[2]; v0.w = p1.y + bs0[3];
        v1.x = p2.x + bs1[0]; v1.y = p2.y + bs1[1];
        v1.z = p3.x + bs1[2]; v1.w = p3.y + bs1[3];
        float* po = &out[(size_t)(m0 + tm + i) * HD + o0 + tc];
        *(float4*)po        = v0;
        *(float4*)(po + 64) = v1;
    }
}

// ---------------------------------------------------------------------------
// Kernel 2: persistent recurrence, batch-row partitioned, octet dataflow.
// Block bx: ng = bx>>5 (rows [16ng,+16)), ot = bx&31 (cols [32ot,+32)).
// Per step: each warp stages its 2 rows of h_{t-1} octet-by-octet as the 8
// producers of that 256-k octet finish (own octet first), then full-K GEMM
// (warp = 64 kp strip, lane = 4n x 4o), 8-warp smem reduce + xh + tanh,
// write h_t, arrive on own octet counter.
// Smem: BsA/BsB ULL[512][16] (2x64KB, conflict-free b) | As2 (swizzled) | Pr.
// ---------------------------------------------------------------------------
#define AS2_ULL (512 * 17 + 4)
#define RNN_SMEM_BYTES ((512 * 16 * 2 + AS2_ULL) * 8 + 8 * 16 * 36 * 4)

__global__ __launch_bounds__(256) void rnn_persistent(
    const float* __restrict__ Whh, float* __restrict__ out)
{
    extern __shared__ char smraw[];
    ULL*   BsA = (ULL*)smraw;                 // [kp][16]: o pairs (4g,4g+1)
    ULL*   BsB = BsA + 512 * 16;              // [kp][16]: o pairs (4g+2,4g+3)
    ULL*   As2 = BsB + 512 * 16;              // [kp][n] stride 17 + swizzle
    float* Pr  = (float*)(As2 + AS2_ULL);     // [w][n][o] stride 36

    const int bx   = blockIdx.x;
    const int ng   = bx >> 5;
    const int ot   = bx & 31;
    const int n0   = ng * 16;
    const int o0   = ot * 32;
    const int tid  = threadIdx.x;
    const int w    = tid >> 5;
    const int lane = tid & 31;
    const int ogl  = lane >> 2;   // 0..7 -> o cols [4ogl, 4ogl+4)
    const int ngl  = lane & 3;    // 0..3 -> n rows [4ngl, 4ngl+4)
    const int myoct = ot >> 3;

    // ---- load W_hh slice once into BsA/BsB ----
    {
        const int o  = tid & 31;          // col within tile
        const int g  = o >> 2, j = o & 3;
        const int its = tid >> 5;         // 8 strips of 128 k
        ULL* dst = (j < 2 ? BsA : BsB) + 2 * g + (j & 1);
        const float* wr = Whh + (size_t)(o0 + o) * HD + its * 128;
        #pragma unroll
        for (int m = 0; m < 32; m++) {
            const float4 v = *(const float4*)(wr + 4 * m);
            const int kp = its * 64 + 2 * m;
            dst[(size_t)kp * 16]       = pack2(v.x, v.y);
            dst[(size_t)(kp + 1) * 16] = pack2(v.z, v.w);
        }
    }

    // ---- epoch -> counter base ----
    __shared__ unsigned s_e;
    if (tid == 0) s_e = *(volatile unsigned*)&g_epoch;
    __syncthreads();
    const unsigned e = s_e;
    const unsigned base = 4096u * e;

    // reduce/tanh mapping: thread -> (row n0+rn, float2 at o0+ro)
    const int rn = tid >> 4;
    const int ro = (tid & 15) << 1;

    // staging mapping: warp stages rows {2w, 2w+(l>>4)}; lane column l&15
    const int srow = 2 * w + (lane >> 4);
    const int scol = lane & 15;

    // ---- t = 0: h_0 = tanh(xh_0) on my slab ----
    {
        float* p = out + (size_t)(n0 + rn) * LH + o0 + ro;
        float2 v = *(float2*)p;
        v.x = tanhf(v.x); v.y = tanhf(v.y);
        *(float2*)p = v;
    }
    __threadfence();
    __syncthreads();
    if (tid == 0) atomicAdd(&g_oct[(ng * 4 + myoct) * 8], 1u);

    for (int t = 1; t < LSEQ; t++) {
        // xh prefetch (DRAM-resident by now; consumed after GEMM)
        float* po = out + (size_t)(n0 + rn) * LH + (size_t)t * HD + o0 + ro;
        const float2 xhv = *(const float2*)po;

        // ---- octet dataflow staging: own octet first ----
        const float* hrow = out + (size_t)(n0 + srow) * LH + (size_t)(t - 1) * HD;
        #pragma unroll
        for (int gp = 0; gp < 4; gp++) {
            const int g = (myoct + gp) & 3;
            if (lane == 0) {
                const unsigned tgt = base + 8u * (unsigned)t;
                while ((int)(*(volatile unsigned*)&g_oct[(ng * 4 + g) * 8] - tgt) < 0) { }
            }
            __syncwarp();
            const int koct = g << 8;
            #pragma unroll
            for (int j = 0; j < 4; j++) {
                const int k  = koct + 4 * scol + 64 * j;
                const float4 v = *(const float4*)(hrow + k);
                const int kp = k >> 1;
                const int sz = (kp >> 4) & 1;
                As2[(size_t)kp * 17 + srow + sz]       = pack2(v.x, v.y);
                As2[(size_t)(kp + 1) * 17 + srow + sz] = pack2(v.z, v.w);
            }
        }
        __syncthreads();

        // ---- full-K GEMM: warp strip kp in [64w, 64w+64) ----
        ULL acc[4][4];
        #pragma unroll
        for (int i = 0; i < 4; i++)
            #pragma unroll
            for (int j = 0; j < 4; j++) acc[i][j] = 0ULL;

        {
            const int kw = 64 * w;
            #pragma unroll 4
            for (int kp = 0; kp < 64; kp++) {
                const int kg = kw + kp;
                const ULL* ap = As2 + (size_t)kg * 17 + 4 * ngl + ((kg >> 4) & 1);
                const ULL a0 = ap[0], a1 = ap[1], a2 = ap[2], a3 = ap[3];
                const ulonglong2 ba = *(const ulonglong2*)(BsA + (size_t)kg * 16 + 2 * ogl);
                const ulonglong2 bb = *(const ulonglong2*)(BsB + (size_t)kg * 16 + 2 * ogl);
                ffma2(acc[0][0], a0, ba.x); ffma2(acc[0][1], a0, ba.y);
                ffma2(acc[0][2], a0, bb.x); ffma2(acc[0][3], a0, bb.y);
                ffma2(acc[1][0], a1, ba.x); ffma2(acc[1][1], a1, ba.y);
                ffma2(acc[1][2], a1, bb.x); ffma2(acc[1][3], a1, bb.y);
                ffma2(acc[2][0], a2, ba.x); ffma2(acc[2][1], a2, ba.y);
                ffma2(acc[2][2], a2, bb.x); ffma2(acc[2][3], a2, bb.y);
                ffma2(acc[3][0], a3, ba.x); ffma2(acc[3][1], a3, ba.y);
                ffma2(acc[3][2], a3, bb.x); ffma2(acc[3][3], a3, bb.y);
            }
        }

        // ---- horizontal add, park warp partials in Pr[w][n][o] (float2) ----
        #pragma unroll
        for (int i = 0; i < 4; i++) {
            const float2 q0 = unpack2(acc[i][0]);
            const float2 q1 = unpack2(acc[i][1]);
            const float2 q2 = unpack2(acc[i][2]);
            const float2 q3 = unpack2(acc[i][3]);
            float2 lo, hi;
            lo.x = q0.x + q0.y; lo.y = q1.x + q1.y;
            hi.x = q2.x + q2.y; hi.y = q3.x + q3.y;
            float* pp = &Pr[(w * 16 + 4 * ngl + i) * 36 + 4 * ogl];
            *(float2*)pp       = lo;
            *(float2*)(pp + 2) = hi;
        }
        __syncthreads();

        // ---- reduce 8 warps + xh, tanh, write h_t ----
        {
            float2 s = make_float2(0.f, 0.f);
            #pragma unroll
            for (int ww = 0; ww < 8; ww++) {
                const float2 v = *(const float2*)&Pr[(ww * 16 + rn) * 36 + ro];
                s.x += v.x; s.y += v.y;
            }
            float2 h;
            h.x = tanhf(s.x + xhv.x);
            h.y = tanhf(s.y + xhv.y);
            *(float2*)po = h;
        }

        __threadfence();
        __syncthreads();
        if (tid == 0) atomicAdd(&g_oct[(ng * 4 + myoct) * 8], 1u);
    }

    // ---- end-of-replay quiesce: only block 0's thread 0 blocks ----
    if (tid == 0) atomicAdd(&g_end, 1u);
    if (bx == 0 && tid == 0) {
        const unsigned tgt = 128u * (e + 1u);
        while ((int)(*(volatile unsigned*)&g_end - tgt) < 0) { }
        *(volatile unsigned*)&g_epoch = e + 1u;
    }
}

// ---------------------------------------------------------------------------
// Launch: metadata order is x, emb, W_hh_w, W_hh_b, W_xh_w, W_xh_b.
// Graph: exactly 2 kernel nodes.
// ---------------------------------------------------------------------------
extern "C" void kernel_launch(void* const* d_in, const int* in_sizes, int n_in,
                              void* d_out, int out_size)
{
    const int*   x     = (const int*)  d_in[0];
    const float* emb   = (const float*)d_in[1];
    const float* Whh_w = (const float*)d_in[2];
    const float* Whh_b = (const float*)d_in[3];
    const float* Wxh_w = (const float*)d_in[4];
    const float* Wxh_b = (const float*)d_in[5];
    float* out = (float*)d_out;

    dim3 g1(HD / 128, (NB * LSEQ) / 128);   // (8, 256)
    xh_kernel<<<g1, 256>>>(x, emb, Wxh_w, Wxh_b, Whh_b, out);

    cudaFuncSetAttribute(rnn_persistent,
                         cudaFuncAttributeMaxDynamicSharedMemorySize,
                         RNN_SMEM_BYTES);
    rnn_persistent<<<NBLK, 256, RNN_SMEM_BYTES>>>(Whh_w, out);
}

// round 13
// speedup vs baseline: 1.7920x; 1.0307x over previous
#include <cuda_runtime.h>
#include <cuda_bf16.h>
#include <math.h>

// Problem constants
#define NB   64
#define LSEQ 512
#define HD   1024
#define LH   (LSEQ * HD)
#define NBLK 128          // 4 n-groups (16 rows) x 32 o-tiles (32 cols)

typedef unsigned long long ULL;

// Octet arrival counters: g_oct[ng][oct] (32B apart). Producer (ng,ot) arrives
// on oct = ot>>3 once per step => counter +8 per step, +4096 per replay.
__device__ unsigned g_oct[4 * 4 * 8];
__device__ unsigned g_end;     // end-of-replay quiesce
__device__ unsigned g_epoch;   // completed replay count

// ---------------------------------------------------------------------------
// Packed f32x2 helpers (FFMA2 — 2 exact fp32 MACs per issue)
// ---------------------------------------------------------------------------
__device__ __forceinline__ void ffma2(ULL& d, ULL a, ULL b)
{
    asm("fma.rn.f32x2 %0, %1, %2, %0;" : "+l"(d) : "l"(a), "l"(b));
}
__device__ __forceinline__ ULL rep2(float v)
{
    ULL r;
    asm("mov.b64 %0, {%1, %1};" : "=l"(r) : "f"(v));
    return r;
}
__device__ __forceinline__ ULL pack2(float x, float y)
{
    ULL r;
    asm("mov.b64 %0, {%1, %2};" : "=l"(r) : "f"(x), "f"(y));
    return r;
}
__device__ __forceinline__ float2 unpack2(ULL v)
{
    float2 f;
    asm("mov.b64 {%0, %1}, %2;" : "=f"(f.x), "=f"(f.y) : "l"(v));
    return f;
}

// ---------------------------------------------------------------------------
// Kernel 1: xh[m][o] = sum_h emb[x[m]][h] * Wxh[o][h] + bxh[o] + bhh[o]
// (unchanged — 128x128 tile, 8x8 microtile on f32x2, at its FFMA2 floor)
// ---------------------------------------------------------------------------
__global__ __launch_bounds__(256) void xh_kernel(
    const int* __restrict__ x, const float* __restrict__ emb,
    const float* __restrict__ Wxh, const float* __restrict__ bxh,
    const float* __restrict__ bhh, float* __restrict__ out)
{
    __shared__ float As[16][132];
    __shared__ float Bs[16][132];
    __shared__ int   toks[128];

    const int m0 = blockIdx.y * 128;
    const int o0 = blockIdx.x * 128;
    const int tid = threadIdx.x;

    if (tid < 128) toks[tid] = x[m0 + tid];
    __syncthreads();

    const int lr  = tid & 127;
    const int lkq = (tid >> 7) << 3;
    const int tm  = (tid >> 4) << 3;
    const int tc  = (tid & 15) << 2;

    const float* Erow = emb + (size_t)toks[lr] * HD + lkq;
    const float* Wrow = Wxh + (size_t)(o0 + lr) * HD + lkq;

    ULL acc[8][4];
    #pragma unroll
    for (int i = 0; i < 8; i++)
        #pragma unroll
        for (int j = 0; j < 4; j++) acc[i][j] = 0ULL;

    for (int k0 = 0; k0 < HD; k0 += 16) {
        const float4 a0 = *(const float4*)(Erow + k0);
        const float4 a1 = *(const float4*)(Erow + k0 + 4);
        const float4 b0 = *(const float4*)(Wrow + k0);
        const float4 b1 = *(const float4*)(Wrow + k0 + 4);
        __syncthreads();
        As[lkq + 0][lr] = a0.x; As[lkq + 1][lr] = a0.y;
        As[lkq + 2][lr] = a0.z; As[lkq + 3][lr] = a0.w;
        As[lkq + 4][lr] = a1.x; As[lkq + 5][lr] = a1.y;
        As[lkq + 6][lr] = a1.z; As[lkq + 7][lr] = a1.w;
        Bs[lkq + 0][lr] = b0.x; Bs[lkq + 1][lr] = b0.y;
        Bs[lkq + 2][lr] = b0.z; Bs[lkq + 3][lr] = b0.w;
        Bs[lkq + 4][lr] = b1.x; Bs[lkq + 5][lr] = b1.y;
        Bs[lkq + 6][lr] = b1.z; Bs[lkq + 7][lr] = b1.w;
        __syncthreads();

        #pragma unroll
        for (int kk = 0; kk < 16; kk++) {
            const float4 av0 = *(const float4*)&As[kk][tm];
            const float4 av1 = *(const float4*)&As[kk][tm + 4];
            ULL ar[8];
            ar[0] = rep2(av0.x); ar[1] = rep2(av0.y);
            ar[2] = rep2(av0.z); ar[3] = rep2(av0.w);
            ar[4] = rep2(av1.x); ar[5] = rep2(av1.y);
            ar[6] = rep2(av1.z); ar[7] = rep2(av1.w);
            const ulonglong2 bq0 = *(const ulonglong2*)&Bs[kk][tc];
            const ulonglong2 bq1 = *(const ulonglong2*)&Bs[kk][64 + tc];
            #pragma unroll
            for (int i = 0; i < 8; i++) {
                ffma2(acc[i][0], ar[i], bq0.x);
                ffma2(acc[i][1], ar[i], bq0.y);
                ffma2(acc[i][2], ar[i], bq1.x);
                ffma2(acc[i][3], ar[i], bq1.y);
            }
        }
    }

    const float4 bxa = *(const float4*)&bxh[o0 + tc];
    const float4 bxb = *(const float4*)&bxh[o0 + 64 + tc];
    const float4 bha = *(const float4*)&bhh[o0 + tc];
    const float4 bhb = *(const float4*)&bhh[o0 + 64 + tc];
    const float bs0[4] = {bxa.x + bha.x, bxa.y + bha.y, bxa.z + bha.z, bxa.w + bha.w};
    const float bs1[4] = {bxb.x + bhb.x, bxb.y + bhb.y, bxb.z + bhb.z, bxb.w + bhb.w};

    #pragma unroll
    for (int i = 0; i < 8; i++) {
        const float2 p0 = unpack2(acc[i][0]);
        const float2 p1 = unpack2(acc[i][1]);
        const float2 p2 = unpack2(acc[i][2]);
        const float2 p3 = unpack2(acc[i][3]);
        float4 v0, v1;
        v0.x = p0.x + bs0[0]; v0.y = p0.y + bs0[1];
        v0.z = p1.x + bs0[2]; v0.w = p1.y + bs0[3];
        v1.x = p2.x + bs1[0]; v1.y = p2.y + bs1[1];
        v1.z = p3.x + bs1[2]; v1.w = p3.y + bs1[3];
        float* po = &out[(size_t)(m0 + tm + i) * HD + o0 + tc];
        *(float4*)po        = v0;
        *(float4*)(po + 64) = v1;
    }
}

// ---------------------------------------------------------------------------
// Kernel 2: persistent recurrence, batch-row partitioned, PAIR-scoped octets.
// Block bx: ng = bx>>5 (rows [16ng,+16)), ot = bx&31 (cols [32ot,+32)).
// Warp w consumes exactly k in [128w,128w+128) = half of octet g = w>>1.
// Warp-pair (2g,2g+1) owns octet g: waits only on that octet's 8 producers,
// stages its 16x256 h-slice (coalesced: lane = contiguous float4, row = j),
// syncs via 64-thread named barrier, then GEMM. Pairs run independently;
// block-wide sync only around the 8-warp reduce.
// Smem: BsA/BsB ULL[512][16] (conflict-free b) | As2 (swizzled) | Pr.
// ---------------------------------------------------------------------------
#define AS2_ULL (512 * 17 + 4)
#define RNN_SMEM_BYTES ((512 * 16 * 2 + AS2_ULL) * 8 + 8 * 16 * 36 * 4)

__global__ __launch_bounds__(256) void rnn_persistent(
    const float* __restrict__ Whh, float* __restrict__ out)
{
    extern __shared__ char smraw[];
    ULL*   BsA = (ULL*)smraw;                 // [kp][16]: o pairs (4g,4g+1)
    ULL*   BsB = BsA + 512 * 16;              // [kp][16]: o pairs (4g+2,4g+3)
    ULL*   As2 = BsB + 512 * 16;              // [kp][n] stride 17 + swizzle
    float* Pr  = (float*)(As2 + AS2_ULL);     // [w][n][o] stride 36

    const int bx   = blockIdx.x;
    const int ng   = bx >> 5;
    const int ot   = bx & 31;
    const int n0   = ng * 16;
    const int o0   = ot * 32;
    const int tid  = threadIdx.x;
    const int w    = tid >> 5;
    const int lane = tid & 31;
    const int ogl  = lane >> 2;   // 0..7 -> o cols [4ogl, 4ogl+4)
    const int ngl  = lane & 3;    // 0..3 -> n rows [4ngl, 4ngl+4)
    const int myoct = ot >> 3;
    const int g    = w >> 1;                  // octet owned by my warp pair
    const int idx  = ((w & 1) << 5) | lane;   // 0..63 within pair

    // ---- load W_hh slice once into BsA/BsB ----
    {
        const int o  = tid & 31;
        const int gg = o >> 2, j = o & 3;
        const int its = tid >> 5;
        ULL* dst = (j < 2 ? BsA : BsB) + 2 * gg + (j & 1);
        const float* wr = Whh + (size_t)(o0 + o) * HD + its * 128;
        #pragma unroll
        for (int m = 0; m < 32; m++) {
            const float4 v = *(const float4*)(wr + 4 * m);
            const int kp = its * 64 + 2 * m;
            dst[(size_t)kp * 16]       = pack2(v.x, v.y);
            dst[(size_t)(kp + 1) * 16] = pack2(v.z, v.w);
        }
    }

    // ---- epoch -> counter base ----
    __shared__ unsigned s_e;
    if (tid == 0) s_e = *(volatile unsigned*)&g_epoch;
    __syncthreads();
    const unsigned e = s_e;
    const unsigned base = 4096u * e;

    // reduce/tanh mapping: thread -> (row n0+rn, float2 at o0+ro)
    const int rn = tid >> 4;
    const int ro = (tid & 15) << 1;

    // staging: my float4 column within octet g (floats [4idx, 4idx+4))
    const int kst = (g << 8) + (idx << 2);    // absolute k of my float4
    const int kp0 = kst >> 1;                 // As2 kp for my float4
    const int sz0 = (kp0 >> 4) & 1;           // swizzle (constant per thread)

    // ---- t = 0: h_0 = tanh(xh_0) on my slab ----
    {
        float* p = out + (size_t)(n0 + rn) * LH + o0 + ro;
        float2 v = *(float2*)p;
        v.x = tanhf(v.x); v.y = tanhf(v.y);
        *(float2*)p = v;
    }
    __threadfence();
    __syncthreads();
    if (tid == 0) atomicAdd(&g_oct[(ng * 4 + myoct) * 8], 1u);

    for (int t = 1; t < LSEQ; t++) {
        // xh prefetch (consumed after GEMM)
        float* po = out + (size_t)(n0 + rn) * LH + (size_t)t * HD + o0 + ro;
        const float2 xhv = *(const float2*)po;

        // ---- pair-scoped wait: only my octet's 8 producers ----
        if (lane == 0) {
            const unsigned tgt = base + 8u * (unsigned)t;
            while ((int)(*(volatile unsigned*)&g_oct[(ng * 4 + g) * 8] - tgt) < 0) { }
        }
        __syncwarp();

        // ---- stage octet g: 16 rows x 256 k, lane = contiguous float4 ----
        const float* hbase = out + (size_t)(t - 1) * HD + kst;
        #pragma unroll
        for (int jj = 0; jj < 16; jj += 8) {
            float4 vb[8];
            #pragma unroll
            for (int j2 = 0; j2 < 8; j2++)
                vb[j2] = __ldcg((const float4*)(hbase + (size_t)(n0 + jj + j2) * LH));
            #pragma unroll
            for (int j2 = 0; j2 < 8; j2++) {
                const int row = jj + j2;
                As2[(size_t)kp0 * 17 + row + sz0]       = pack2(vb[j2].x, vb[j2].y);
                As2[(size_t)(kp0 + 1) * 17 + row + sz0] = pack2(vb[j2].z, vb[j2].w);
            }
        }
        // pair barrier (64 threads): STS drained, both warps' staging visible
        asm volatile("bar.sync %0, %1;" :: "r"(g + 1), "r"(64) : "memory");

        // ---- full-K GEMM: warp strip kp in [64w, 64w+64) (inside octet g) ----
        ULL acc[4][4];
        #pragma unroll
        for (int i = 0; i < 4; i++)
            #pragma unroll
            for (int j = 0; j < 4; j++) acc[i][j] = 0ULL;

        {
            const int kw = 64 * w;
            #pragma unroll 4
            for (int kp = 0; kp < 64; kp++) {
                const int kg = kw + kp;
                const ULL* ap = As2 + (size_t)kg * 17 + 4 * ngl + ((kg >> 4) & 1);
                const ULL a0 = ap[0], a1 = ap[1], a2 = ap[2], a3 = ap[3];
                const ulonglong2 ba = *(const ulonglong2*)(BsA + (size_t)kg * 16 + 2 * ogl);
                const ulonglong2 bb = *(const ulonglong2*)(BsB + (size_t)kg * 16 + 2 * ogl);
                ffma2(acc[0][0], a0, ba.x); ffma2(acc[0][1], a0, ba.y);
                ffma2(acc[0][2], a0, bb.x); ffma2(acc[0][3], a0, bb.y);
                ffma2(acc[1][0], a1, ba.x); ffma2(acc[1][1], a1, ba.y);
                ffma2(acc[1][2], a1, bb.x); ffma2(acc[1][3], a1, bb.y);
                ffma2(acc[2][0], a2, ba.x); ffma2(acc[2][1], a2, ba.y);
                ffma2(acc[2][2], a2, bb.x); ffma2(acc[2][3], a2, bb.y);
                ffma2(acc[3][0], a3, ba.x); ffma2(acc[3][1], a3, ba.y);
                ffma2(acc[3][2], a3, bb.x); ffma2(acc[3][3], a3, bb.y);
            }
        }

        // ---- horizontal add, park warp partials in Pr[w][n][o] ----
        #pragma unroll
        for (int i = 0; i < 4; i++) {
            const float2 q0 = unpack2(acc[i][0]);
            const float2 q1 = unpack2(acc[i][1]);
            const float2 q2 = unpack2(acc[i][2]);
            const float2 q3 = unpack2(acc[i][3]);
            float2 lo, hi;
            lo.x = q0.x + q0.y; lo.y = q1.x + q1.y;
            hi.x = q2.x + q2.y; hi.y = q3.x + q3.y;
            float* pp = &Pr[(w * 16 + 4 * ngl + i) * 36 + 4 * ogl];
            *(float2*)pp       = lo;
            *(float2*)(pp + 2) = hi;
        }
        __syncthreads();

        // ---- reduce 8 warps + xh, tanh, write h_t ----
        {
            float2 s = make_float2(0.f, 0.f);
            #pragma unroll
            for (int ww = 0; ww < 8; ww++) {
                const float2 v = *(const float2*)&Pr[(ww * 16 + rn) * 36 + ro];
                s.x += v.x; s.y += v.y;
            }
            float2 h;
            h.x = tanhf(s.x + xhv.x);
            h.y = tanhf(s.y + xhv.y);
            *(float2*)po = h;
        }

        __threadfence();
        __syncthreads();   // h_t visible; also protects Pr/As2 WAR for next step
        if (tid == 0) atomicAdd(&g_oct[(ng * 4 + myoct) * 8], 1u);
    }

    // ---- end-of-replay quiesce: only block 0's thread 0 blocks ----
    if (tid == 0) atomicAdd(&g_end, 1u);
    if (bx == 0 && tid == 0) {
        const unsigned tgt = 128u * (e + 1u);
        while ((int)(*(volatile unsigned*)&g_end - tgt) < 0) { }
        *(volatile unsigned*)&g_epoch = e + 1u;
    }
}

// ---------------------------------------------------------------------------
// Launch: metadata order is x, emb, W_hh_w, W_hh_b, W_xh_w, W_xh_b.
// Graph: exactly 2 kernel nodes.
// ---------------------------------------------------------------------------
extern "C" void kernel_launch(void* const* d_in, const int* in_sizes, int n_in,
                              void* d_out, int out_size)
{
    const int*   x     = (const int*)  d_in[0];
    const float* emb   = (const float*)d_in[1];
    const float* Whh_w = (const float*)d_in[2];
    const float* Whh_b = (const float*)d_in[3];
    const float* Wxh_w = (const float*)d_in[4];
    const float* Wxh_b = (const float*)d_in[5];
    float* out = (float*)d_out;

    dim3 g1(HD / 128, (NB * LSEQ) / 128);   // (8, 256)
    xh_kernel<<<g1, 256>>>(x, emb, Wxh_w, Wxh_b, Whh_b, out);

    cudaFuncSetAttribute(rnn_persistent,
                         cudaFuncAttributeMaxDynamicSharedMemorySize,
                         RNN_SMEM_BYTES);
    rnn_persistent<<<NBLK, 256, RNN_SMEM_BYTES>>>(Whh_w, out);
}